// round 10
// baseline (speedup 1.0000x reference)
#include <cuda_runtime.h>
#include <cuda_bf16.h>
#include <cstdint>

#define NNODES 20000
#define NEDGES 160000
#define F_IN   512
#define F_HID  512
#define F_OUT  256

// ---------------- scratch ----------------------------------------------------
__device__ int   g_is64;
__device__ int   g_deg[NNODES];
__device__ int   g_rowptr[NNODES + 1];
__device__ int   g_cursor[NNODES];
__device__ int   g_srcs[NEDGES];
__device__ __align__(16) float g_dinv[NNODES];
__device__ __align__(16) float g_h1[(size_t)NNODES * F_HID];
__device__ __align__(16) float g_a1[(size_t)NNODES * F_HID];
__device__ __align__(16) float g_h2[(size_t)NNODES * F_OUT];

// ---------------- preprocessing ---------------------------------------------
__global__ void detect_zero_kernel(const int* ei) {
    const int i = blockIdx.x * blockDim.x + threadIdx.x;
    if (i == 0) {
        int is64 = 1;
        for (int k = 1; k < 64; k += 2)
            if (ei[k] != 0) { is64 = 0; break; }
        g_is64 = is64;
    }
    if (i < NNODES) g_deg[i] = 0;
}

__global__ void deg_count_kernel(const void* ei) {
    const int e = blockIdx.x * blockDim.x + threadIdx.x;
    if (e < NEDGES) {
        int dst;
        if (g_is64) dst = (int)((const long long*)ei)[NEDGES + e];
        else        dst = ((const int*)ei)[NEDGES + e];
        atomicAdd(&g_deg[dst], 1);
    }
}

__global__ void scan_dinv_kernel() {
    __shared__ int part[1024];
    const int t = threadIdx.x;
    const int CH = (NNODES + 1023) / 1024;
    const int base = t * CH;
    int s = 0;
    for (int i = 0; i < CH; i++) {
        int idx = base + i;
        if (idx < NNODES) s += g_deg[idx];
    }
    part[t] = s;
    __syncthreads();
    for (int off = 1; off < 1024; off <<= 1) {
        int v = (t >= off) ? part[t - off] : 0;
        __syncthreads();
        part[t] += v;
        __syncthreads();
    }
    int run = (t > 0) ? part[t - 1] : 0;
    for (int i = 0; i < CH; i++) {
        int idx = base + i;
        if (idx < NNODES) {
            g_rowptr[idx] = run;
            g_cursor[idx] = run;
            g_dinv[idx] = rsqrtf(1.0f + (float)g_deg[idx]);
            run += g_deg[idx];
        }
    }
    if (t == 1023) g_rowptr[NNODES] = part[1023];
}

__global__ void fill_kernel(const void* ei) {
    const int e = blockIdx.x * blockDim.x + threadIdx.x;
    if (e < NEDGES) {
        int src, dst;
        if (g_is64) {
            const long long* p = (const long long*)ei;
            src = (int)p[e]; dst = (int)p[NEDGES + e];
        } else {
            const int* p = (const int*)ei;
            src = p[e]; dst = p[NEDGES + e];
        }
        int pos = atomicAdd(&g_cursor[dst], 1);
        g_srcs[pos] = src;
    }
}

template <int F>
__global__ void scale_rows_kernel(float* __restrict__ h) {
    const int total4 = NNODES * F / 4;
    for (int idx = blockIdx.x * blockDim.x + threadIdx.x; idx < total4;
         idx += gridDim.x * blockDim.x) {
        const int node = idx / (F / 4);
        const float d = g_dinv[node];
        float4 v = reinterpret_cast<float4*>(h)[idx];
        v.x *= d; v.y *= d; v.z *= d; v.w *= d;
        reinterpret_cast<float4*>(h)[idx] = v;
    }
}

// ---------------- SIMT fp32 GEMM, 128x128x8, 8x8/thread (restored R8) -------
template <bool SCALE_OUT>
__global__ __launch_bounds__(256, 2)
void sgemm128_kernel(const float* __restrict__ A, const float* __restrict__ B,
                     float* __restrict__ C, int M, int N, int K) {
    constexpr int BM = 128, BN = 128, BK = 8;
    __shared__ float As[2][BK][BM];
    __shared__ float Bs[2][BK][BN];

    const int tid = threadIdx.x;
    const int block_row = blockIdx.y * BM;
    const int block_col = blockIdx.x * BN;

    const int a_row  = tid >> 1;
    const int a_col4 = (tid & 1) * 4;
    const int b_row  = tid >> 5;
    const int b_col4 = (tid & 31) * 4;

    const int ty = tid >> 4;
    const int tx = tid & 15;

    const int a_g_row = block_row + a_row;
    const bool a_ok = a_g_row < M;
    const float* a_ptr = A + (size_t)(a_ok ? a_g_row : 0) * K + a_col4;
    const float* b_ptr = B + (size_t)b_row * N + block_col + b_col4;

    float acc[8][8];
    #pragma unroll
    for (int i = 0; i < 8; i++)
        #pragma unroll
        for (int j = 0; j < 8; j++) acc[i][j] = 0.f;

    {
        float4 av = a_ok ? *reinterpret_cast<const float4*>(a_ptr)
                         : make_float4(0.f, 0.f, 0.f, 0.f);
        float4 bv = *reinterpret_cast<const float4*>(b_ptr);
        As[0][a_col4 + 0][a_row] = av.x;
        As[0][a_col4 + 1][a_row] = av.y;
        As[0][a_col4 + 2][a_row] = av.z;
        As[0][a_col4 + 3][a_row] = av.w;
        *reinterpret_cast<float4*>(&Bs[0][b_row][b_col4]) = bv;
    }
    __syncthreads();

    const int nsteps = K / BK;
    for (int k0 = 0; k0 < nsteps; k0++) {
        const int buf = k0 & 1;
        float4 av, bv;
        const bool has_next = (k0 + 1) < nsteps;
        if (has_next) {
            const float* ap = a_ptr + (size_t)(k0 + 1) * BK;
            av = a_ok ? *reinterpret_cast<const float4*>(ap)
                      : make_float4(0.f, 0.f, 0.f, 0.f);
            bv = *reinterpret_cast<const float4*>(b_ptr + (size_t)(k0 + 1) * BK * N);
        }

        #pragma unroll
        for (int k = 0; k < BK; k++) {
            float4 ra0 = *reinterpret_cast<const float4*>(&As[buf][k][ty * 4]);
            float4 ra1 = *reinterpret_cast<const float4*>(&As[buf][k][ty * 4 + 64]);
            float4 rb0 = *reinterpret_cast<const float4*>(&Bs[buf][k][tx * 4]);
            float4 rb1 = *reinterpret_cast<const float4*>(&Bs[buf][k][tx * 4 + 64]);
            const float ra[8] = {ra0.x, ra0.y, ra0.z, ra0.w, ra1.x, ra1.y, ra1.z, ra1.w};
            const float rb[8] = {rb0.x, rb0.y, rb0.z, rb0.w, rb1.x, rb1.y, rb1.z, rb1.w};
            #pragma unroll
            for (int i = 0; i < 8; i++)
                #pragma unroll
                for (int j = 0; j < 8; j++) acc[i][j] += ra[i] * rb[j];
        }

        if (has_next) {
            const int nb = buf ^ 1;
            As[nb][a_col4 + 0][a_row] = av.x;
            As[nb][a_col4 + 1][a_row] = av.y;
            As[nb][a_col4 + 2][a_row] = av.z;
            As[nb][a_col4 + 3][a_row] = av.w;
            *reinterpret_cast<float4*>(&Bs[nb][b_row][b_col4]) = bv;
            __syncthreads();
        }
    }

    #pragma unroll
    for (int i = 0; i < 8; i++) {
        const int lr = (i < 4) ? (ty * 4 + i) : (64 + ty * 4 + i - 4);
        const int gr = block_row + lr;
        if (gr < M) {
            const float d = SCALE_OUT ? g_dinv[gr] : 1.0f;
            float4 v0 = make_float4(acc[i][0] * d, acc[i][1] * d, acc[i][2] * d, acc[i][3] * d);
            float4 v1 = make_float4(acc[i][4] * d, acc[i][5] * d, acc[i][6] * d, acc[i][7] * d);
            *reinterpret_cast<float4*>(C + (size_t)gr * N + block_col + tx * 4) = v0;
            *reinterpret_cast<float4*>(C + (size_t)gr * N + block_col + 64 + tx * 4) = v1;
        }
    }
}

// ---------------- pull aggregation over pre-scaled rows (UNCHANGED R8) ------
// Pure function of (h, rowptr, srcs, dinv, bias) -> out. Idempotent: running
// it twice produces the identical result, which this round exploits to
// measure its true in-graph cost via dur_us deltas.
template <int F>
__global__ void aggregate_warp_kernel(const float* __restrict__ h,
                                      const float* __restrict__ bias,
                                      float* __restrict__ out) {
    constexpr int NV = F / 128;
    const int w    = threadIdx.x >> 5;
    const int lane = threadIdx.x & 31;
    const int v = blockIdx.x * 8 + w;
    if (v >= NNODES) return;

    const float dv = g_dinv[v];

    float4 acc[NV];
    {
        const float4* hv = reinterpret_cast<const float4*>(h + (size_t)v * F);
        #pragma unroll
        for (int i = 0; i < NV; i++) acc[i] = __ldg(&hv[lane + 32 * i]);
    }

    const int beg = g_rowptr[v];
    const int end = g_rowptr[v + 1];
    int j = beg;
    for (; j + 4 <= end; j += 4) {
        const int s0 = __ldg(&g_srcs[j + 0]);
        const int s1 = __ldg(&g_srcs[j + 1]);
        const int s2 = __ldg(&g_srcs[j + 2]);
        const int s3 = __ldg(&g_srcs[j + 3]);
        const float4* p0 = reinterpret_cast<const float4*>(h + (size_t)s0 * F);
        const float4* p1 = reinterpret_cast<const float4*>(h + (size_t)s1 * F);
        const float4* p2 = reinterpret_cast<const float4*>(h + (size_t)s2 * F);
        const float4* p3 = reinterpret_cast<const float4*>(h + (size_t)s3 * F);
        #pragma unroll
        for (int i = 0; i < NV; i++) {
            const int c = lane + 32 * i;
            float4 t0 = __ldg(&p0[c]);
            float4 t1 = __ldg(&p1[c]);
            float4 t2 = __ldg(&p2[c]);
            float4 t3 = __ldg(&p3[c]);
            acc[i].x += (t0.x + t1.x) + (t2.x + t3.x);
            acc[i].y += (t0.y + t1.y) + (t2.y + t3.y);
            acc[i].z += (t0.z + t1.z) + (t2.z + t3.z);
            acc[i].w += (t0.w + t1.w) + (t2.w + t3.w);
        }
    }
    for (; j < end; j++) {
        const int s = __ldg(&g_srcs[j]);
        const float4* p = reinterpret_cast<const float4*>(h + (size_t)s * F);
        #pragma unroll
        for (int i = 0; i < NV; i++) {
            float4 t = __ldg(&p[lane + 32 * i]);
            acc[i].x += t.x; acc[i].y += t.y; acc[i].z += t.z; acc[i].w += t.w;
        }
    }

    const float4* bptr = reinterpret_cast<const float4*>(bias);
    float4* optr = reinterpret_cast<float4*>(out + (size_t)v * F);
    #pragma unroll
    for (int i = 0; i < NV; i++) {
        float4 b = bptr[lane + 32 * i];
        float4 o;
        o.x = fmaxf(acc[i].x * dv + b.x, 0.f);
        o.y = fmaxf(acc[i].y * dv + b.y, 0.f);
        o.z = fmaxf(acc[i].z * dv + b.z, 0.f);
        o.w = fmaxf(acc[i].w * dv + b.w, 0.f);
        optr[lane + 32 * i] = o;
    }
}

// ---------------- launch ----------------------------------------------------
// R8 structure with SIMT GEMM restored, PLUS each aggregate launched twice
// (idempotent -> identical output). dur_us delta vs the single-launch
// baseline (~3995us) measures the aggregates' real in-graph cost:
//   total ~= 3995 + agg1 + agg2.
extern "C" void kernel_launch(void* const* d_in, const int* in_sizes, int n_in,
                              void* d_out, int out_size) {
    const float* x  = (const float*)d_in[0];
    const void*  ei = d_in[1];
    const float* W1 = (const float*)d_in[2];
    const float* b1 = (const float*)d_in[3];
    const float* W2 = (const float*)d_in[4];
    const float* b2 = (const float*)d_in[5];
    float* out = (float*)d_out;

    detect_zero_kernel<<<(NNODES + 255) / 256, 256>>>((const int*)ei);   // 0
    deg_count_kernel<<<(NEDGES + 255) / 256, 256>>>(ei);                 // 1
    scan_dinv_kernel<<<1, 1024>>>();                                     // 2
    fill_kernel<<<(NEDGES + 255) / 256, 256>>>(ei);                      // 3 (capture)

    {                                                                    // 4
        dim3 grid(F_HID / 128, (NNODES + 127) / 128);
        sgemm128_kernel<false><<<grid, 256>>>(x, W1, g_h1, NNODES, F_HID, F_IN);
    }
    scale_rows_kernel<F_HID><<<2048, 256>>>(g_h1);                       // 5
    aggregate_warp_kernel<F_HID><<<(NNODES + 7) / 8, 256>>>(g_h1, b1, g_a1);  // 6
    aggregate_warp_kernel<F_HID><<<(NNODES + 7) / 8, 256>>>(g_h1, b1, g_a1);  // 7 (dup)

    {                                                                    // 8
        dim3 grid(F_OUT / 128, (NNODES + 127) / 128);
        sgemm128_kernel<true><<<grid, 256>>>(g_a1, W2, g_h2, NNODES, F_OUT, F_HID);
    }
    aggregate_warp_kernel<F_OUT><<<(NNODES + 7) / 8, 256>>>(g_h2, b2, out);   // 9
    aggregate_warp_kernel<F_OUT><<<(NNODES + 7) / 8, 256>>>(g_h2, b2, out);   // 10 (dup)
}